// round 2
// baseline (speedup 1.0000x reference)
#include <cuda_runtime.h>
#include <cstdint>

#define SDIM  16
#define NNODE 256
#define VDIM  64
#define EDIM  64
#define HDIM  16
#define KEDGE 255   // N-1

// per-node projections, pr stored TRANSPOSED: g_prT[s][e][n]
__device__ float g_prT[SDIM * HDIM * NNODE];
__device__ float g_psb[SDIM * NNODE * HDIM];   // psb[sn][e] = v0@we1[64:128] + be1

__device__ __forceinline__ float fast_tanh(float x) {
    // tanh(x) = 1 - 2/(e^{2x}+1); robust at +/-inf, MUFU-based, ~1e-6 rel err
    float y = __expf(2.0f * x);
    return 1.0f - __fdividef(2.0f, y + 1.0f);
}

// ---------------------------------------------------------------------------
// Kernel 1: one block per (s,n).
//   ev = sum_k e0[s,n,k,:]            (the 267MB streaming read)
//   dv = tanh(ev@wv1+bv1)@wv2+bv2     -> out
//   prT (transposed), psb per node    -> scratch
// ---------------------------------------------------------------------------
__global__ void __launch_bounds__(256) node_kernel(
    const float* __restrict__ v0,
    const float* __restrict__ e0,
    const float* __restrict__ wv1, const float* __restrict__ bv1,
    const float* __restrict__ wv2, const float* __restrict__ bv2,
    const float* __restrict__ we1, const float* __restrict__ be1,
    float* __restrict__ dv_out)
{
    const int sn  = blockIdx.x;           // s*256 + n
    const int tid = threadIdx.x;          // 256 threads

    __shared__ float4 part[16][17];       // [k-group][c4], padded
    __shared__ float  evs[EDIM];
    __shared__ float  vs [VDIM];
    __shared__ float  hv [HDIM];

    // --- phase A: strided float4 reduction of e0 over k (streaming) ---
    const float4* e0p = reinterpret_cast<const float4*>(e0) + (size_t)sn * (KEDGE * EDIM / 4);
    const int c4 = tid & 15;              // which float4 of the 64-wide channel dim
    const int kg = tid >> 4;              // k-group 0..15
    float4 acc = make_float4(0.f, 0.f, 0.f, 0.f);
    #pragma unroll 8
    for (int k = kg; k < KEDGE; k += 16) {
        float4 v = __ldcs(&e0p[k * 16 + c4]);
        acc.x += v.x; acc.y += v.y; acc.z += v.z; acc.w += v.w;
    }
    part[kg][c4] = acc;
    __syncthreads();

    if (tid < 16) {
        float4 s = part[0][tid];
        #pragma unroll
        for (int g = 1; g < 16; g++) {
            float4 p = part[g][tid];
            s.x += p.x; s.y += p.y; s.z += p.z; s.w += p.w;
        }
        reinterpret_cast<float4*>(evs)[tid] = s;
    } else if (tid < 32) {
        reinterpret_cast<float4*>(vs)[tid - 16] =
            reinterpret_cast<const float4*>(v0)[sn * 16 + (tid - 16)];
    }
    __syncthreads();

    // --- phase B: tiny per-node matmuls ---
    const int s_idx = sn >> 8;
    const int n_idx = sn & 255;
    if (tid < 16) {
        float a = bv1[tid];
        #pragma unroll
        for (int e = 0; e < EDIM; e++) a = fmaf(evs[e], wv1[e * HDIM + tid], a);
        hv[tid] = fast_tanh(a);
    } else if (tid < 32) {
        int j = tid - 16;
        float a = 0.f;
        #pragma unroll
        for (int e = 0; e < VDIM; e++) a = fmaf(vs[e], we1[e * HDIM + j], a);
        g_prT[(s_idx * HDIM + j) * NNODE + n_idx] = a;   // transposed
    } else if (tid < 48) {
        int j = tid - 32;
        float a = be1[j];
        #pragma unroll
        for (int e = 0; e < VDIM; e++) a = fmaf(vs[e], we1[(VDIM + e) * HDIM + j], a);
        g_psb[sn * HDIM + j] = a;
    }
    __syncthreads();

    if (tid < VDIM) {
        float a = bv2[tid];
        #pragma unroll
        for (int j = 0; j < HDIM; j++) a = fmaf(hv[j], wv2[j * VDIM + tid], a);
        dv_out[(size_t)sn * VDIM + tid] = a;
    }
}

// ---------------------------------------------------------------------------
// Kernel 2: one block per (s,i).
// Phase 1: thread k (<255) computes t[k][0..15] = tanh(prT[e][j]+psb[e]),
//          j = k + (k>=i); stores DUPLICATED f32x2 pairs into tdupT[pair][k]
//          (transposed layout -> contiguous STS.128, broadcast LDS in phase 2).
// Phase 2: 16 groups x 16 lanes; lane owns 4 output channels, weights in regs;
//          inner loop = LDS.128 (two e's) + 4 x fma.rn.f32x2. No shfl.
// ---------------------------------------------------------------------------
__global__ void __launch_bounds__(256, 2) edge_kernel(
    const float* __restrict__ we2, const float* __restrict__ be2,
    float* __restrict__ de_out)
{
    const int sn  = blockIdx.x;           // s*256 + i
    const int s   = sn >> 8;
    const int i   = sn & 255;
    const int tid = threadIdx.x;

    __shared__ float      prT[HDIM][NNODE];        // 16 KB
    __shared__ float      psb_s[HDIM];
    __shared__ ulonglong2 tdupT[8][KEDGE];         // 31.9 KB: [e-pair][edge]

    // stage prT for this s (coalesced float4, conflict-free)
    {
        const float4* src = reinterpret_cast<const float4*>(g_prT + s * HDIM * NNODE);
        float4*       dst = reinterpret_cast<float4*>(&prT[0][0]);
        #pragma unroll
        for (int q = 0; q < 4; q++) dst[tid + 256 * q] = src[tid + 256 * q];
    }
    if (tid < 4) {
        reinterpret_cast<float4*>(psb_s)[tid] =
            reinterpret_cast<const float4*>(g_psb + sn * HDIM)[tid];
    }
    __syncthreads();

    // --- phase 1: per-edge tanh, duplicated-pair store ---
    if (tid < KEDGE) {
        const int j = tid + (tid >= i);            // skip diagonal
        #pragma unroll
        for (int m = 0; m < 8; m++) {
            float x0 = prT[2 * m    ][j] + psb_s[2 * m    ];
            float x1 = prT[2 * m + 1][j] + psb_s[2 * m + 1];
            float t0 = fast_tanh(x0);
            float t1 = fast_tanh(x1);
            unsigned long long u0, u1;
            asm("mov.b64 %0, {%1, %1};" : "=l"(u0) : "f"(t0));
            asm("mov.b64 %0, {%1, %1};" : "=l"(u1) : "f"(t1));
            tdupT[m][tid] = make_ulonglong2(u0, u1);   // STS.128, contiguous
        }
    }

    // weights for this lane: channels 4l..4l+3, all 16 h-dims, packed f32x2
    const int l = tid & 15;               // lane within group == channel quad
    const int g = tid >> 4;               // edge group 0..15
    unsigned long long w0[16], w1[16], B0, B1;
    #pragma unroll
    for (int e = 0; e < HDIM; e++) {
        float4 w = reinterpret_cast<const float4*>(we2)[e * 16 + l];
        asm("mov.b64 %0, {%1, %2};" : "=l"(w0[e]) : "f"(w.x), "f"(w.y));
        asm("mov.b64 %0, {%1, %2};" : "=l"(w1[e]) : "f"(w.z), "f"(w.w));
    }
    {
        float4 b = reinterpret_cast<const float4*>(be2)[l];
        asm("mov.b64 %0, {%1, %2};" : "=l"(B0) : "f"(b.x), "f"(b.y));
        asm("mov.b64 %0, {%1, %2};" : "=l"(B1) : "f"(b.z), "f"(b.w));
    }
    __syncthreads();

    float* outbase = de_out + (size_t)sn * KEDGE * VDIM + l * 4;

    #pragma unroll 1
    for (int iter = 0; iter < 16; iter++) {
        const int k  = iter * 16 + g;
        const int kc = (k < KEDGE) ? k : (KEDGE - 1);   // clamp inactive tail

        unsigned long long A0 = B0, A1 = B1;
        #pragma unroll
        for (int m = 0; m < 8; m++) {
            ulonglong2 tt = tdupT[m][kc];               // LDS.128, 16-lane broadcast
            asm("fma.rn.f32x2 %0, %1, %2, %0;" : "+l"(A0) : "l"(w0[2 * m    ]), "l"(tt.x));
            asm("fma.rn.f32x2 %0, %1, %2, %0;" : "+l"(A1) : "l"(w1[2 * m    ]), "l"(tt.x));
            asm("fma.rn.f32x2 %0, %1, %2, %0;" : "+l"(A0) : "l"(w0[2 * m + 1]), "l"(tt.y));
            asm("fma.rn.f32x2 %0, %1, %2, %0;" : "+l"(A1) : "l"(w1[2 * m + 1]), "l"(tt.y));
        }

        if (k < KEDGE) {
            float4 o;
            asm("mov.b64 {%0, %1}, %2;" : "=f"(o.x), "=f"(o.y) : "l"(A0));
            asm("mov.b64 {%0, %1}, %2;" : "=f"(o.z), "=f"(o.w) : "l"(A1));
            __stcs(reinterpret_cast<float4*>(outbase + (size_t)k * VDIM), o);
        }
    }
}

// ---------------------------------------------------------------------------
// inputs (metadata order): t, v0, e0, wv1, bv1, wv2, bv2, we1, be1, we2, be2,
//                          recv_idx, send_idx (idx arrays unused: analytic)
// output: dv (S,N,V) followed by de (S,N,N-1,E)
// ---------------------------------------------------------------------------
extern "C" void kernel_launch(void* const* d_in, const int* in_sizes, int n_in,
                              void* d_out, int out_size)
{
    const float* v0  = (const float*)d_in[1];
    const float* e0  = (const float*)d_in[2];
    const float* wv1 = (const float*)d_in[3];
    const float* bv1 = (const float*)d_in[4];
    const float* wv2 = (const float*)d_in[5];
    const float* bv2 = (const float*)d_in[6];
    const float* we1 = (const float*)d_in[7];
    const float* be1 = (const float*)d_in[8];
    const float* we2 = (const float*)d_in[9];
    const float* be2 = (const float*)d_in[10];

    float* dv_out = (float*)d_out;
    float* de_out = dv_out + (size_t)SDIM * NNODE * VDIM;

    node_kernel<<<SDIM * NNODE, 256>>>(v0, e0, wv1, bv1, wv2, bv2, we1, be1, dv_out);
    edge_kernel<<<SDIM * NNODE, 256>>>(we2, be2, de_out);
}

// round 3
// speedup vs baseline: 1.0381x; 1.0381x over previous
#include <cuda_runtime.h>
#include <cstdint>

#define SDIM  16
#define NNODE 256
#define VDIM  64
#define EDIM  64
#define HDIM  16
#define KEDGE 255   // N-1

typedef unsigned long long ull;

// per-node projections, pr stored TRANSPOSED: g_prT[s][e][n]
__device__ float g_prT[SDIM * HDIM * NNODE];
__device__ float g_psb[SDIM * NNODE * HDIM];   // psb[sn][e] = v0@we1[64:128] + be1

__device__ __forceinline__ float fast_tanh(float x) {
    // tanh(x) = 1 - 2/(e^{2x}+1); robust at +/-inf, MUFU-based, ~1e-6 rel err
    float y = __expf(2.0f * x);
    return 1.0f - __fdividef(2.0f, y + 1.0f);
}

// ---------------------------------------------------------------------------
// Kernel A: per-node projections (tiny).  one block per (s,n), 64 threads.
//   pr[j]  = v0[sn] @ we1[0:64, j]        (stored transposed: g_prT[s][j][n])
//   psb[j] = v0[sn] @ we1[64:128, j] + be1[j]
// ---------------------------------------------------------------------------
__global__ void __launch_bounds__(64) proj_kernel(
    const float* __restrict__ v0,
    const float* __restrict__ we1, const float* __restrict__ be1)
{
    const int sn  = blockIdx.x;
    const int tid = threadIdx.x;
    __shared__ float vs[VDIM];

    vs[tid] = v0[(size_t)sn * VDIM + tid];
    __syncthreads();

    const int s_idx = sn >> 8;
    const int n_idx = sn & 255;
    if (tid < 16) {
        float a = 0.f;
        #pragma unroll
        for (int e = 0; e < VDIM; e++) a = fmaf(vs[e], we1[e * HDIM + tid], a);
        g_prT[(s_idx * HDIM + tid) * NNODE + n_idx] = a;
    } else if (tid < 32) {
        int j = tid - 16;
        float a = be1[j];
        #pragma unroll
        for (int e = 0; e < VDIM; e++) a = fmaf(vs[e], we1[(VDIM + e) * HDIM + j], a);
        g_psb[sn * HDIM + j] = a;
    }
}

// ---------------------------------------------------------------------------
// Kernel B: fused. grid = 8192; even bid -> node path, odd bid -> edge path.
// Node path (per (s,n)): ev = sum_k e0[s,n,k,:] (267MB streaming read),
//                        dv = tanh(ev@wv1+bv1)@wv2+bv2.
// Edge path (per (s,i)): phase1 - thread k computes t[k][e]=tanh(prT[e][j]+psb[e]),
//                        j=k+(k>=i), stores duplicated f32x2 into smem tdup.
//                        phase2 - 8 warps; lane owns 2 channels (16 packed
//                        weights in regs); per edge: 8 bcast LDS.128 + 16 FFMA2
//                        + STG.64 streaming store (267MB write).
// Mixing both paths in one launch keeps reads and writes in flight together.
// ---------------------------------------------------------------------------
__global__ void __launch_bounds__(256, 3) fused_kernel(
    const float* __restrict__ e0,
    const float* __restrict__ wv1, const float* __restrict__ bv1,
    const float* __restrict__ wv2, const float* __restrict__ bv2,
    const float* __restrict__ we2, const float* __restrict__ be2,
    float* __restrict__ dv_out, float* __restrict__ de_out)
{
    __shared__ union SM {
        struct { float4 part[16][17]; float evs[EDIM]; float hv[HDIM]; } node;
        struct { ulonglong2 tdup[8][256]; float psb[HDIM]; } edge;
    } sm;

    const int bid = blockIdx.x;
    const int sn  = bid >> 1;             // s*256 + n(i)
    const int tid = threadIdx.x;

    if ((bid & 1) == 0) {
        // ================= node path =================
        const float4* e0p = reinterpret_cast<const float4*>(e0)
                          + (size_t)sn * (KEDGE * EDIM / 4);
        const int c4 = tid & 15;          // float4 index within 64-wide channel
        const int kg = tid >> 4;          // k-group 0..15
        float4 acc = make_float4(0.f, 0.f, 0.f, 0.f);
        #pragma unroll 8
        for (int k = kg; k < KEDGE; k += 16) {
            float4 v = __ldcs(&e0p[k * 16 + c4]);
            acc.x += v.x; acc.y += v.y; acc.z += v.z; acc.w += v.w;
        }
        sm.node.part[kg][c4] = acc;
        __syncthreads();

        if (tid < 16) {
            float4 a = sm.node.part[0][tid];
            #pragma unroll
            for (int g = 1; g < 16; g++) {
                float4 p = sm.node.part[g][tid];
                a.x += p.x; a.y += p.y; a.z += p.z; a.w += p.w;
            }
            reinterpret_cast<float4*>(sm.node.evs)[tid] = a;
        }
        __syncthreads();

        if (tid < 16) {
            float a = bv1[tid];
            #pragma unroll
            for (int e = 0; e < EDIM; e++) a = fmaf(sm.node.evs[e], wv1[e * HDIM + tid], a);
            sm.node.hv[tid] = fast_tanh(a);
        }
        __syncthreads();

        if (tid < VDIM) {
            float a = bv2[tid];
            #pragma unroll
            for (int j = 0; j < HDIM; j++) a = fmaf(sm.node.hv[j], wv2[j * VDIM + tid], a);
            dv_out[(size_t)sn * VDIM + tid] = a;
        }
    } else {
        // ================= edge path =================
        const int s = sn >> 8;
        const int i = sn & 255;

        if (tid < 4) {
            reinterpret_cast<float4*>(sm.edge.psb)[tid] =
                reinterpret_cast<const float4*>(g_psb + sn * HDIM)[tid];
        }

        // lane-private packed weights (channels 2l, 2l+1 for all 16 h-dims)
        const int l = tid & 31;
        const int w = tid >> 5;
        ull wr[16], B;
        #pragma unroll
        for (int e = 0; e < HDIM; e++) {
            float2 wf = reinterpret_cast<const float2*>(we2)[e * 32 + l];
            asm("mov.b64 %0, {%1, %2};" : "=l"(wr[e]) : "f"(wf.x), "f"(wf.y));
        }
        {
            float2 bf = reinterpret_cast<const float2*>(be2)[l];
            asm("mov.b64 %0, {%1, %2};" : "=l"(B) : "f"(bf.x), "f"(bf.y));
        }
        __syncthreads();

        // --- phase 1: per-edge tanh, duplicated-pair store ---
        if (tid < KEDGE) {
            const int j = tid + (tid >= i);           // skip diagonal
            const float* prb = g_prT + s * HDIM * NNODE + j;
            #pragma unroll
            for (int m = 0; m < 8; m++) {
                float x0 = __ldg(prb + (2 * m    ) * NNODE) + sm.edge.psb[2 * m    ];
                float x1 = __ldg(prb + (2 * m + 1) * NNODE) + sm.edge.psb[2 * m + 1];
                float t0 = fast_tanh(x0);
                float t1 = fast_tanh(x1);
                ull u0, u1;
                asm("mov.b64 %0, {%1, %1};" : "=l"(u0) : "f"(t0));
                asm("mov.b64 %0, {%1, %1};" : "=l"(u1) : "f"(t1));
                sm.edge.tdup[m][tid] = make_ulonglong2(u0, u1);
            }
        }
        __syncthreads();

        // --- phase 2: GEMM row per edge, warp-broadcast t ---
        float* outbase = de_out + (size_t)sn * KEDGE * VDIM + l * 2;
        #pragma unroll 1
        for (int iter = 0; iter < 32; iter++) {
            const int k = iter * 8 + w;               // warp-uniform edge id
            if (k < KEDGE) {
                ull A = B;
                #pragma unroll
                for (int m = 0; m < 8; m++) {
                    ulonglong2 tt = sm.edge.tdup[m][k]; // LDS.128, 32-lane broadcast
                    asm("fma.rn.f32x2 %0, %1, %2, %0;" : "+l"(A) : "l"(wr[2 * m    ]), "l"(tt.x));
                    asm("fma.rn.f32x2 %0, %1, %2, %0;" : "+l"(A) : "l"(wr[2 * m + 1]), "l"(tt.y));
                }
                float2 o;
                asm("mov.b64 {%0, %1}, %2;" : "=f"(o.x), "=f"(o.y) : "l"(A));
                __stcs(reinterpret_cast<float2*>(outbase + (size_t)k * VDIM), o);
            }
        }
    }
}

// ---------------------------------------------------------------------------
// inputs (metadata order): t, v0, e0, wv1, bv1, wv2, bv2, we1, be1, we2, be2,
//                          recv_idx, send_idx (idx arrays unused: analytic)
// output: dv (S,N,V) followed by de (S,N,N-1,E)
// ---------------------------------------------------------------------------
extern "C" void kernel_launch(void* const* d_in, const int* in_sizes, int n_in,
                              void* d_out, int out_size)
{
    const float* v0  = (const float*)d_in[1];
    const float* e0  = (const float*)d_in[2];
    const float* wv1 = (const float*)d_in[3];
    const float* bv1 = (const float*)d_in[4];
    const float* wv2 = (const float*)d_in[5];
    const float* bv2 = (const float*)d_in[6];
    const float* we1 = (const float*)d_in[7];
    const float* be1 = (const float*)d_in[8];
    const float* we2 = (const float*)d_in[9];
    const float* be2 = (const float*)d_in[10];

    float* dv_out = (float*)d_out;
    float* de_out = dv_out + (size_t)SDIM * NNODE * VDIM;

    proj_kernel<<<SDIM * NNODE, 64>>>(v0, we1, be1);
    fused_kernel<<<2 * SDIM * NNODE, 256>>>(e0, wv1, bv1, wv2, bv2, we2, be2,
                                            dv_out, de_out);
}

// round 4
// speedup vs baseline: 1.1802x; 1.1368x over previous
#include <cuda_runtime.h>
#include <cstdint>

#define SDIM  16
#define NNODE 256
#define VDIM  64
#define EDIM  64
#define HDIM  16
#define KEDGE 255   // N-1

typedef unsigned long long ull;

// per-node projections, pr stored TRANSPOSED: g_prT[s][e][n]
__device__ float g_prT[SDIM * HDIM * NNODE];
__device__ float g_psb[SDIM * NNODE * HDIM];   // psb[sn][e] = v0@we1[64:128] + be1

__device__ __forceinline__ float fast_tanh(float x) {
    // tanh(x) = 1 - 2/(e^{2x}+1); robust at +/-inf, MUFU-based, ~1e-6 rel err
    float y = __expf(2.0f * x);
    return 1.0f - __fdividef(2.0f, y + 1.0f);
}
__device__ __forceinline__ ull dup2(float t) {
    ull u; asm("mov.b64 %0, {%1, %1};" : "=l"(u) : "f"(t)); return u;
}
__device__ __forceinline__ ull pack2(float a, float b) {
    ull u; asm("mov.b64 %0, {%1, %2};" : "=l"(u) : "f"(a), "f"(b)); return u;
}

// ---------------------------------------------------------------------------
// Kernel A: per-node projections (tiny). one block per (s,n), 64 threads.
// ---------------------------------------------------------------------------
__global__ void __launch_bounds__(64) proj_kernel(
    const float* __restrict__ v0,
    const float* __restrict__ we1, const float* __restrict__ be1)
{
    const int sn  = blockIdx.x;
    const int tid = threadIdx.x;
    __shared__ float vs[VDIM];

    vs[tid] = v0[(size_t)sn * VDIM + tid];
    __syncthreads();

    const int s_idx = sn >> 8;
    const int n_idx = sn & 255;
    if (tid < 16) {
        float a = 0.f;
        #pragma unroll
        for (int e = 0; e < VDIM; e++) a = fmaf(vs[e], we1[e * HDIM + tid], a);
        g_prT[(s_idx * HDIM + tid) * NNODE + n_idx] = a;
    } else if (tid < 32) {
        int j = tid - 16;
        float a = be1[j];
        #pragma unroll
        for (int e = 0; e < VDIM; e++) a = fmaf(vs[e], we1[(VDIM + e) * HDIM + j], a);
        g_psb[sn * HDIM + j] = a;
    }
}

// ---------------------------------------------------------------------------
// Mega kernel: one block per (s,n). Each warp interleaves BOTH streams:
//  - e0 row reads (267MB) in register batches of 4 (MLP=4, consumed 8 edge
//    iters later -> ~450cyc self-hiding per batch)
//  - edge GEMM + de stores (267MB): lane owns 2 channels (16 packed f32x2
//    weights in regs), t[e] from smem tanh table (broadcast LDS.128),
//    accumulator chain split in two.
// Epilogue reuses tdup smem for the node reduction + tiny MLPs.
// ---------------------------------------------------------------------------
__global__ void __launch_bounds__(256, 3) mega_kernel(
    const float* __restrict__ e0,
    const float* __restrict__ wv1, const float* __restrict__ bv1,
    const float* __restrict__ wv2, const float* __restrict__ bv2,
    const float* __restrict__ we2, const float* __restrict__ be2,
    float* __restrict__ dv_out, float* __restrict__ de_out)
{
    __shared__ union SM {
        struct { ulonglong2 tdup[8][256]; } edge;                    // 32 KB
        struct { float4 part[16][17]; float evs[EDIM]; float hv[HDIM]; } node;
    } sm;
    __shared__ float psb_s[HDIM];

    const int sn  = blockIdx.x;           // s*256 + n  (n is also edge-row i)
    const int s   = sn >> 8;
    const int i   = sn & 255;
    const int tid = threadIdx.x;
    const int w   = tid >> 5;             // warp 0..7
    const int l   = tid & 31;             // lane
    const int c4  = l & 15;               // float4 slot in 64-wide channel dim
    const int r0  = w * 2 + (l >> 4);     // 0..15: row offset within 16-row groups

    const float4* e0p = reinterpret_cast<const float4*>(e0)
                      + (size_t)sn * (KEDGE * EDIM / 4);

    // issue read batch 0 immediately (lands during tanh-table phase)
    float4 buf[4];
    #pragma unroll
    for (int j = 0; j < 4; j++)
        buf[j] = __ldcs(&e0p[(j * 16 + r0) * 16 + c4]);      // rows 0..63 region

    if (tid < 4)
        reinterpret_cast<float4*>(psb_s)[tid] =
            reinterpret_cast<const float4*>(g_psb + sn * HDIM)[tid];

    // lane-private packed weights: channels 2l, 2l+1 for all 16 h-dims
    ull wr[16], B;
    #pragma unroll
    for (int e = 0; e < HDIM; e++) {
        float2 wf = reinterpret_cast<const float2*>(we2)[e * 32 + l];
        wr[e] = pack2(wf.x, wf.y);
    }
    {
        float2 bf = reinterpret_cast<const float2*>(be2)[l];
        B = pack2(bf.x, bf.y);
    }
    __syncthreads();                       // psb_s visible

    // --- tanh table: thread k computes t[k][0..15], stores duplicated pairs ---
    if (tid < KEDGE) {
        const int j = tid + (tid >= i);    // skip diagonal
        const float* prb = g_prT + s * HDIM * NNODE + j;
        #pragma unroll
        for (int m = 0; m < 8; m++) {
            float x0 = __ldg(prb + (2 * m    ) * NNODE) + psb_s[2 * m    ];
            float x1 = __ldg(prb + (2 * m + 1) * NNODE) + psb_s[2 * m + 1];
            sm.edge.tdup[m][tid] =
                make_ulonglong2(dup2(fast_tanh(x0)), dup2(fast_tanh(x1)));
        }
    }
    __syncthreads();                       // table ready

    float4 acc = make_float4(0.f, 0.f, 0.f, 0.f);
    float* outp = de_out + (size_t)sn * KEDGE * VDIM + l * 2;

    // --- main loop: 4 batches x (8 edge iters + consume batch + issue next) ---
    #pragma unroll 1
    for (int b = 0; b < 4; b++) {
        #pragma unroll 1
        for (int q = 0; q < 8; q++) {
            const int k = (b * 8 + q) * 8 + w;             // edge id 0..255
            if (k < KEDGE) {
                ull A0 = B, A1 = 0;                        // split chains
                #pragma unroll
                for (int m = 0; m < 4; m++) {
                    ulonglong2 tt = sm.edge.tdup[m][k];    // broadcast LDS.128
                    asm("fma.rn.f32x2 %0, %1, %2, %0;" : "+l"(A0) : "l"(wr[2*m  ]), "l"(tt.x));
                    asm("fma.rn.f32x2 %0, %1, %2, %0;" : "+l"(A0) : "l"(wr[2*m+1]), "l"(tt.y));
                }
                #pragma unroll
                for (int m = 4; m < 8; m++) {
                    ulonglong2 tt = sm.edge.tdup[m][k];
                    asm("fma.rn.f32x2 %0, %1, %2, %0;" : "+l"(A1) : "l"(wr[2*m  ]), "l"(tt.x));
                    asm("fma.rn.f32x2 %0, %1, %2, %0;" : "+l"(A1) : "l"(wr[2*m+1]), "l"(tt.y));
                }
                asm("add.rn.f32x2 %0, %0, %1;" : "+l"(A0) : "l"(A1));
                float2 o;
                asm("mov.b64 {%0, %1}, %2;" : "=f"(o.x), "=f"(o.y) : "l"(A0));
                __stcs(reinterpret_cast<float2*>(outp + (size_t)k * VDIM), o);
            }
        }
        // consume batch b
        #pragma unroll
        for (int j = 0; j < 4; j++) {
            const int r = (b * 4 + j) * 16 + r0;
            if (r < KEDGE) {
                acc.x += buf[j].x; acc.y += buf[j].y;
                acc.z += buf[j].z; acc.w += buf[j].w;
            }
        }
        // issue batch b+1
        if (b < 3) {
            #pragma unroll
            for (int j = 0; j < 4; j++) {
                const int r = ((b + 1) * 4 + j) * 16 + r0;
                if (r < KEDGE) buf[j] = __ldcs(&e0p[r * 16 + c4]);
            }
        }
    }

    // --- node epilogue: reduce partials (reuse tdup smem), tiny MLPs ---
    __syncthreads();                       // everyone done reading tdup
    sm.node.part[r0][c4] = acc;            // 16 owners x 16 c4 slots
    __syncthreads();

    if (tid < 16) {
        float4 a = sm.node.part[0][tid];
        #pragma unroll
        for (int g = 1; g < 16; g++) {
            float4 p = sm.node.part[g][tid];
            a.x += p.x; a.y += p.y; a.z += p.z; a.w += p.w;
        }
        reinterpret_cast<float4*>(sm.node.evs)[tid] = a;
    }
    __syncthreads();

    if (tid < 16) {
        float a = bv1[tid];
        #pragma unroll
        for (int e = 0; e < EDIM; e++) a = fmaf(sm.node.evs[e], wv1[e * HDIM + tid], a);
        sm.node.hv[tid] = fast_tanh(a);
    }
    __syncthreads();

    if (tid < VDIM) {
        float a = bv2[tid];
        #pragma unroll
        for (int j = 0; j < HDIM; j++) a = fmaf(sm.node.hv[j], wv2[j * VDIM + tid], a);
        dv_out[(size_t)sn * VDIM + tid] = a;
    }
}

// ---------------------------------------------------------------------------
// inputs (metadata order): t, v0, e0, wv1, bv1, wv2, bv2, we1, be1, we2, be2,
//                          recv_idx, send_idx (idx arrays unused: analytic)
// output: dv (S,N,V) followed by de (S,N,N-1,E)
// ---------------------------------------------------------------------------
extern "C" void kernel_launch(void* const* d_in, const int* in_sizes, int n_in,
                              void* d_out, int out_size)
{
    const float* v0  = (const float*)d_in[1];
    const float* e0  = (const float*)d_in[2];
    const float* wv1 = (const float*)d_in[3];
    const float* bv1 = (const float*)d_in[4];
    const float* wv2 = (const float*)d_in[5];
    const float* bv2 = (const float*)d_in[6];
    const float* we1 = (const float*)d_in[7];
    const float* be1 = (const float*)d_in[8];
    const float* we2 = (const float*)d_in[9];
    const float* be2 = (const float*)d_in[10];

    float* dv_out = (float*)d_out;
    float* de_out = dv_out + (size_t)SDIM * NNODE * VDIM;

    proj_kernel<<<SDIM * NNODE, 64>>>(v0, we1, be1);
    mega_kernel<<<SDIM * NNODE, 256>>>(e0, wv1, bv1, wv2, bv2, we2, be2,
                                       dv_out, de_out);
}